// round 14
// baseline (speedup 1.0000x reference)
#include <cuda_runtime.h>
#include <cstdint>

// SVDHead: batched Kabsch rotation, fused kernel with cp.async.bulk staging.
//   Per block (one batch): thread 0 issues 3 bulk async copies (src 24KB,
//   tgt 24KB, mask 8KB -> 56KB dynamic smem) completing on an mbarrier —
//   bytes-in-flight no longer limited by the register file (R12 analysis:
//   LDG MLP capped at 5.4KB/SM vs ~9KB needed for full HBM rate).
//   All 256 threads then reduce H = src^T diag(mask) tgt from smem
//   (LDS.128, conflict-free at 48B stride), warp 0 finishes and thread 0 runs
//   the branchless MUFU-fast one-sided Jacobi 3x3 SVD (3 sweeps), writing
//   R = V diag(1,1,sgn) U^T (sign on smallest singular pair, sgn=sign(det H)).
//   smem 57.5KB/CTA -> 4 CTAs/SM (32 warps), regs low.
//
// B=4096, N=2048.

#define BB 4096
#define NN 2048
#define THREADS 256

#define SRC_BYTES (NN * 3 * 4)        // 24576
#define MASK_BYTES (NN * 4)           // 8192
#define TX_BYTES (2 * SRC_BYTES + MASK_BYTES)  // 57344

// dynamic smem layout (16B-aligned offsets)
#define SM_MBAR 0
#define SM_SRC  128
#define SM_TGT  (SM_SRC + SRC_BYTES)   // 24704
#define SM_MASK (SM_TGT + SRC_BYTES)   // 49280
#define SM_TOTAL (SM_MASK + MASK_BYTES) // 57472

__global__ __launch_bounds__(THREADS)
void svdhead_tma_kernel(const float* __restrict__ src,
                        const float* __restrict__ tgt,
                        const float* __restrict__ mask_tgt,
                        float* __restrict__ out)
{
    extern __shared__ char smem[];
    const int b    = blockIdx.x;
    const int tid  = threadIdx.x;
    const int lane = tid & 31;
    const int warp = tid >> 5;

    const uint32_t smem_base = (uint32_t)__cvta_generic_to_shared(smem);
    const uint32_t mbar = smem_base + SM_MBAR;

    if (tid == 0) {
        asm volatile("mbarrier.init.shared.b64 [%0], 1;" :: "r"(mbar) : "memory");
        // make the init visible to the async proxy before the bulk ops
        asm volatile("fence.proxy.async.shared::cta;" ::: "memory");
        asm volatile("mbarrier.arrive.expect_tx.shared.b64 _, [%0], %1;"
                     :: "r"(mbar), "r"((uint32_t)TX_BYTES) : "memory");
        const char* gsrc = (const char*)(src)      + (size_t)b * SRC_BYTES;
        const char* gtgt = (const char*)(tgt)      + (size_t)b * SRC_BYTES;
        const char* gmsk = (const char*)(mask_tgt) + (size_t)b * MASK_BYTES;
        asm volatile("cp.async.bulk.shared::cluster.global.mbarrier::complete_tx::bytes "
                     "[%0], [%1], %2, [%3];"
                     :: "r"(smem_base + SM_SRC), "l"(gsrc), "r"((uint32_t)SRC_BYTES), "r"(mbar)
                     : "memory");
        asm volatile("cp.async.bulk.shared::cluster.global.mbarrier::complete_tx::bytes "
                     "[%0], [%1], %2, [%3];"
                     :: "r"(smem_base + SM_TGT), "l"(gtgt), "r"((uint32_t)SRC_BYTES), "r"(mbar)
                     : "memory");
        asm volatile("cp.async.bulk.shared::cluster.global.mbarrier::complete_tx::bytes "
                     "[%0], [%1], %2, [%3];"
                     :: "r"(smem_base + SM_MASK), "l"(gmsk), "r"((uint32_t)MASK_BYTES), "r"(mbar)
                     : "memory");
    }
    __syncthreads();   // all threads see the initialized mbarrier before waiting

    // wait for all 57344 bytes (parity 0; barrier used exactly once)
    {
        uint32_t done;
        asm volatile(
            "{\n\t"
            ".reg .pred p;\n\t"
            "mbarrier.try_wait.parity.shared.b64 p, [%1], 0;\n\t"
            "selp.b32 %0, 1, 0, p;\n\t"
            "}" : "=r"(done) : "r"(mbar) : "memory");
        while (!done) {
            asm volatile(
                "{\n\t"
                ".reg .pred p;\n\t"
                "mbarrier.try_wait.parity.shared.b64 p, [%1], 0, 0x989680;\n\t"
                "selp.b32 %0, 1, 0, p;\n\t"
                "}" : "=r"(done) : "r"(mbar) : "memory");
        }
    }

    // ---- masked outer-product reduction from smem -------------------------
    const float4* s4 = reinterpret_cast<const float4*>(smem + SM_SRC);
    const float4* t4 = reinterpret_cast<const float4*>(smem + SM_TGT);
    const float4* m4 = reinterpret_cast<const float4*>(smem + SM_MASK);

    float h[9];
    #pragma unroll
    for (int i = 0; i < 9; ++i) h[i] = 0.f;

    #define ACC_POINT(sx, sy, sz, tx, ty, tz, mm)                                              \
        {                                                                                      \
            float w0 = (mm) * (tx), w1 = (mm) * (ty), w2 = (mm) * (tz);                        \
            h[0] = fmaf((sx), w0, h[0]); h[1] = fmaf((sx), w1, h[1]); h[2] = fmaf((sx), w2, h[2]); \
            h[3] = fmaf((sy), w0, h[3]); h[4] = fmaf((sy), w1, h[4]); h[5] = fmaf((sy), w2, h[5]); \
            h[6] = fmaf((sz), w0, h[6]); h[7] = fmaf((sz), w1, h[7]); h[8] = fmaf((sz), w2, h[8]); \
        }

    #pragma unroll
    for (int half = 0; half < 2; ++half) {
        const int g = tid + half * THREADS;   // group of 4 points
        float4 sa = s4[g * 3 + 0];
        float4 sb = s4[g * 3 + 1];
        float4 sc = s4[g * 3 + 2];
        float4 ta = t4[g * 3 + 0];
        float4 tb = t4[g * 3 + 1];
        float4 tc = t4[g * 3 + 2];
        float4 m  = m4[g];

        ACC_POINT(sa.x, sa.y, sa.z, ta.x, ta.y, ta.z, m.x)
        ACC_POINT(sa.w, sb.x, sb.y, ta.w, tb.x, tb.y, m.y)
        ACC_POINT(sb.z, sb.w, sc.x, tb.z, tb.w, tc.x, m.z)
        ACC_POINT(sc.y, sc.z, sc.w, tc.y, tc.z, tc.w, m.w)
    }
    #undef ACC_POINT

    // warp reduce
    #pragma unroll
    for (int i = 0; i < 9; ++i) {
        #pragma unroll
        for (int off = 16; off > 0; off >>= 1)
            h[i] += __shfl_down_sync(0xffffffffu, h[i], off);
    }

    __shared__ float red[THREADS / 32][9];
    if (lane == 0) {
        #pragma unroll
        for (int i = 0; i < 9; ++i) red[warp][i] = h[i];
    }
    __syncthreads();

    if (warp == 0) {
        float hv = 0.f;
        if (lane < 9) {
            #pragma unroll
            for (int w = 0; w < THREADS / 32; ++w) hv += red[w][lane];
            red[0][lane] = hv;
        }
        __syncwarp();

        if (lane == 0) {
            float A[3][3], V[3][3];
            #pragma unroll
            for (int r = 0; r < 3; ++r)
                #pragma unroll
                for (int c = 0; c < 3; ++c) {
                    A[r][c] = red[0][r * 3 + c];
                    V[r][c] = (r == c) ? 1.f : 0.f;
                }

            const float det =
                  A[0][0] * (A[1][1] * A[2][2] - A[1][2] * A[2][1])
                - A[0][1] * (A[1][0] * A[2][2] - A[1][2] * A[2][0])
                + A[0][2] * (A[1][0] * A[2][1] - A[1][1] * A[2][0]);

            // one-sided Jacobi, 3 sweeps, fully unrolled, branchless, MUFU-fast.
            #pragma unroll
            for (int sweep = 0; sweep < 3; ++sweep) {
                #pragma unroll
                for (int pq = 0; pq < 3; ++pq) {
                    const int p = (pq == 2) ? 1 : 0;
                    const int q = (pq == 0) ? 1 : 2;
                    float ap0 = A[0][p], ap1 = A[1][p], ap2 = A[2][p];
                    float aq0 = A[0][q], aq1 = A[1][q], aq2 = A[2][q];
                    float alpha = ap0 * ap0 + ap1 * ap1 + ap2 * ap2;
                    float beta  = aq0 * aq0 + aq1 * aq1 + aq2 * aq2;
                    float gamma = ap0 * aq0 + ap1 * aq1 + ap2 * aq2;
                    float gden  = copysignf(fmaxf(fabsf(gamma), 1e-30f), gamma);
                    float zeta  = __fdividef(beta - alpha, 2.f * gden);  // MUFU.RCP
                    float w     = fmaf(zeta, zeta, 1.f);
                    float sqw   = w * rsqrtf(w);                         // MUFU.RSQ
                    float t     = __fdividef(copysignf(1.f, zeta), fabsf(zeta) + sqw);
                    float c     = rsqrtf(fmaf(t, t, 1.f));               // MUFU.RSQ
                    float s     = c * t;
                    #pragma unroll
                    for (int r = 0; r < 3; ++r) {
                        float xp = A[r][p], xq = A[r][q];
                        A[r][p] = c * xp - s * xq;
                        A[r][q] = s * xp + c * xq;
                        float vp = V[r][p], vq = V[r][q];
                        V[r][p] = c * vp - s * vq;
                        V[r][q] = s * vp + c * vq;
                    }
                }
            }

            // singular values = column norms; U columns = normalized A columns
            float U[3][3], sv[3];
            #pragma unroll
            for (int j = 0; j < 3; ++j) {
                float d = A[0][j] * A[0][j] + A[1][j] * A[1][j] + A[2][j] * A[2][j];
                sv[j] = d;
                float inv = rsqrtf(fmaxf(d, 1e-30f));
                U[0][j] = A[0][j] * inv;
                U[1][j] = A[1][j] * inv;
                U[2][j] = A[2][j] * inv;
            }
            int jmin = 0;
            if (sv[1] < sv[jmin]) jmin = 1;
            if (sv[2] < sv[jmin]) jmin = 2;

            const float sgn = (det < 0.f) ? -1.f : 1.f;
            float coef[3] = {1.f, 1.f, 1.f};
            coef[jmin] = sgn;

            // R = V diag(coef) U^T — streaming stores
            float* o = out + (size_t)b * 9;
            #pragma unroll
            for (int i = 0; i < 3; ++i)
                #pragma unroll
                for (int k = 0; k < 3; ++k) {
                    float acc = coef[0] * V[i][0] * U[k][0]
                              + coef[1] * V[i][1] * U[k][1]
                              + coef[2] * V[i][2] * U[k][2];
                    __stcs(&o[i * 3 + k], acc);
                }
        }
    }
}

extern "C" void kernel_launch(void* const* d_in, const int* in_sizes, int n_in,
                              void* d_out, int out_size)
{
    const float* src      = (const float*)d_in[0];  // src_pts3d  [B,N,3]
    const float* tgt      = (const float*)d_in[1];  // tgt_pts3d  [B,N,3]
    // d_in[2] = kpt_src_mask — unused by the reference einsum
    const float* mask_tgt = (const float*)d_in[3];  // kpt_tgt_mask [B,N]
    float* out = (float*)d_out;

    static bool attr_set = false;
    if (!attr_set) {
        cudaFuncSetAttribute(svdhead_tma_kernel,
                             cudaFuncAttributeMaxDynamicSharedMemorySize, SM_TOTAL);
        attr_set = true;
    }
    svdhead_tma_kernel<<<BB, THREADS, SM_TOTAL>>>(src, tgt, mask_tgt, out);
}